// round 17
// baseline (speedup 1.0000x reference)
#include <cuda_runtime.h>
#include <cuda_fp16.h>
#include <stdint.h>
#include <math.h>

#define NB 128      // batch
#define NTT 32      // timesteps
#define NV 32000    // vocab
#define NE 128      // embed dim
#define NH 256      // hidden
#define NF 2048     // feature dim
#define NG 1024     // 4*H (gates)
#define LDW (NE + NF)   // W_ih row stride = 2176

// ---------------- scratch (device globals; no allocation allowed) ------------
__device__ float g_embed[NTT * NB * NE];       // [t][b][e]
__device__ float g_gates_emb[NTT * NB * NG];   // [t][b][j]
__device__ float g_gbase[NB * NG];             // [b][j] (+biases folded in)
__device__ float g_bpart[8 * NG * NB];         // K-split partials for gates_base ([j][b])
__device__ float g_gates[NB * NG];             // per-step gates
__device__ float g_h[NB * NH];
__device__ float g_c[NB * NH];
__device__ float g_Hall[NTT * NB * NH];        // [t][b][h]
__device__ float g_initpart[2 * 8 * NB * NH];  // K-split partials for h0/c0 ([b][h])

// ---------------- helpers ----------------------------------------------------
__device__ __forceinline__ uint32_t packh2(float lo, float hi) {
    uint32_t u;
    asm("cvt.rn.f16x2.f32 %0, %1, %2;" : "=r"(u) : "f"(hi), "f"(lo));
    return u;
}

__device__ __forceinline__ void mma_f16(float* d, const uint32_t* a, const uint32_t* b) {
    asm volatile(
        "mma.sync.aligned.m16n8k16.row.col.f32.f16.f16.f32 "
        "{%0,%1,%2,%3}, {%4,%5,%6,%7}, {%8,%9}, {%0,%1,%2,%3};"
        : "+f"(d[0]), "+f"(d[1]), "+f"(d[2]), "+f"(d[3])
        : "r"(a[0]), "r"(a[1]), "r"(a[2]), "r"(a[3]), "r"(b[0]), "r"(b[1]));
}

// ---------------- gather: g_embed[(t*NB+b)*NE + e] = embeddings[captions[b,t]] ----
__global__ void gather_embed_kernel(const int* __restrict__ captions,
                                    const float* __restrict__ embeddings) {
    int idx = blockIdx.x * blockDim.x + threadIdx.x;
    if (idx >= NTT * NB * NE) return;
    int e = idx % NE;
    int m = idx / NE;          // t*NB + b
    int t = m / NB;
    int b = m % NB;
    int tok = captions[b * NTT + t];
    g_embed[idx] = embeddings[tok * NE + e];
}

// ---------------- init h0/c0: NN gemm with deterministic K-split -------------
__global__ void init_part_kernel(const float* __restrict__ A,   // features (NB, NF)
                                 const float* __restrict__ W,   // (NF, NH)
                                 int mat) {
    __shared__ float As[16][64];
    __shared__ float Bs[16][64];
    int n0 = blockIdx.x * 64;
    int m0 = blockIdx.y * 64;
    int kz = blockIdx.z;
    int tid = threadIdx.x;
    int lm = tid >> 2, lk = (tid & 3) * 4;
    int kr = tid >> 4, n4 = (tid & 15) * 4;
    int tx = tid & 15, ty = tid >> 4;
    float acc[4][4] = {};

    for (int k0 = kz * 256; k0 < kz * 256 + 256; k0 += 16) {
        float4 av = *(const float4*)&A[(size_t)(m0 + lm) * NF + k0 + lk];
        As[lk + 0][lm] = av.x; As[lk + 1][lm] = av.y;
        As[lk + 2][lm] = av.z; As[lk + 3][lm] = av.w;
        float4 bv = *(const float4*)&W[(size_t)(k0 + kr) * NH + n0 + n4];
        *(float4*)&Bs[kr][n4] = bv;
        __syncthreads();
        #pragma unroll
        for (int kk = 0; kk < 16; kk++) {
            float4 a = *(const float4*)&As[kk][ty * 4];
            float4 b = *(const float4*)&Bs[kk][tx * 4];
            float ar[4] = {a.x, a.y, a.z, a.w};
            float br[4] = {b.x, b.y, b.z, b.w};
            #pragma unroll
            for (int i = 0; i < 4; i++)
                #pragma unroll
                for (int j = 0; j < 4; j++)
                    acc[i][j] = fmaf(ar[i], br[j], acc[i][j]);
        }
        __syncthreads();
    }
    float* dst = g_initpart + ((size_t)(mat * 8 + kz) * NB) * NH;
    #pragma unroll
    for (int i = 0; i < 4; i++)
        #pragma unroll
        for (int j = 0; j < 4; j++)
            dst[(size_t)(m0 + ty * 4 + i) * NH + n0 + tx * 4 + j] = acc[i][j];
}

__global__ void init_reduce_kernel(const float* __restrict__ bH,
                                   const float* __restrict__ bC) {
    int idx = blockIdx.x * blockDim.x + threadIdx.x;   // NB*NH, partials [b][h]
    int h = idx & 255;
    float sH = bH[h], sC = bC[h];
    #pragma unroll
    for (int z = 0; z < 8; z++) {
        sH += g_initpart[(size_t)z * NB * NH + idx];
        sC += g_initpart[(size_t)(8 + z) * NB * NH + idx];
    }
    g_h[idx] = sH;
    g_c[idx] = sC;
}

// ---------------- generic NT sgemm: C[M,N] = A(M,K) @ B(N,K)^T (+adds) -------
__global__ void sgemm_nt64(const float* __restrict__ A, int lda,
                           const float* __restrict__ B, int ldb,
                           float* __restrict__ C, int ldc, int K,
                           const float* __restrict__ add1,
                           const float* __restrict__ add2) {
    __shared__ float As[16][64];
    __shared__ float Bs[16][64];
    int m0 = blockIdx.y * 64;
    int n0 = blockIdx.x * 64;
    int tid = threadIdx.x;
    int lm = tid >> 2;
    int lk = (tid & 3) * 4;
    int tx = tid & 15;
    int ty = tid >> 4;
    float acc[4][4] = {};

    for (int k0 = 0; k0 < K; k0 += 16) {
        float4 av = *(const float4*)&A[(size_t)(m0 + lm) * lda + k0 + lk];
        float4 bv = *(const float4*)&B[(size_t)(n0 + lm) * ldb + k0 + lk];
        As[lk + 0][lm] = av.x; As[lk + 1][lm] = av.y;
        As[lk + 2][lm] = av.z; As[lk + 3][lm] = av.w;
        Bs[lk + 0][lm] = bv.x; Bs[lk + 1][lm] = bv.y;
        Bs[lk + 2][lm] = bv.z; Bs[lk + 3][lm] = bv.w;
        __syncthreads();
        #pragma unroll
        for (int kk = 0; kk < 16; kk++) {
            float4 a = *(const float4*)&As[kk][ty * 4];
            float4 b = *(const float4*)&Bs[kk][tx * 4];
            float ar[4] = {a.x, a.y, a.z, a.w};
            float br[4] = {b.x, b.y, b.z, b.w};
            #pragma unroll
            for (int i = 0; i < 4; i++)
                #pragma unroll
                for (int j = 0; j < 4; j++)
                    acc[i][j] = fmaf(ar[i], br[j], acc[i][j]);
        }
        __syncthreads();
    }

    #pragma unroll
    for (int i = 0; i < 4; i++) {
        int m = m0 + ty * 4 + i;
        #pragma unroll
        for (int j = 0; j < 4; j++) {
            int n = n0 + tx * 4 + j;
            float v = acc[i][j];
            if (add1) v += add1[(size_t)m * ldc + n];
            if (add2) v += add2[(size_t)m * ldc + n];
            C[(size_t)m * ldc + n] = v;
        }
    }
}

// ---------------- gates_base: K-split NT gemm (M=NG j-rows, N=NB, K=2048) ----
__global__ void gbase_part_kernel(const float* __restrict__ A,   // W_ih + NE, lda=LDW
                                  const float* __restrict__ B) { // features, ldb=NF
    __shared__ float As[16][64];
    __shared__ float Bs[16][64];
    int n0 = blockIdx.x * 64;   // b
    int m0 = blockIdx.y * 64;   // j
    int kz = blockIdx.z;
    int tid = threadIdx.x;
    int lm = tid >> 2;
    int lk = (tid & 3) * 4;
    int tx = tid & 15;
    int ty = tid >> 4;
    float acc[4][4] = {};

    for (int k0 = kz * 256; k0 < kz * 256 + 256; k0 += 16) {
        float4 av = *(const float4*)&A[(size_t)(m0 + lm) * LDW + k0 + lk];
        float4 bv = *(const float4*)&B[(size_t)(n0 + lm) * NF + k0 + lk];
        As[lk + 0][lm] = av.x; As[lk + 1][lm] = av.y;
        As[lk + 2][lm] = av.z; As[lk + 3][lm] = av.w;
        Bs[lk + 0][lm] = bv.x; Bs[lk + 1][lm] = bv.y;
        Bs[lk + 2][lm] = bv.z; Bs[lk + 3][lm] = bv.w;
        __syncthreads();
        #pragma unroll
        for (int kk = 0; kk < 16; kk++) {
            float4 a = *(const float4*)&As[kk][ty * 4];
            float4 b = *(const float4*)&Bs[kk][tx * 4];
            float ar[4] = {a.x, a.y, a.z, a.w};
            float br[4] = {b.x, b.y, b.z, b.w};
            #pragma unroll
            for (int i = 0; i < 4; i++)
                #pragma unroll
                for (int j = 0; j < 4; j++)
                    acc[i][j] = fmaf(ar[i], br[j], acc[i][j]);
        }
        __syncthreads();
    }
    float* dst = g_bpart + (size_t)kz * NG * NB;
    #pragma unroll
    for (int i = 0; i < 4; i++)
        #pragma unroll
        for (int j = 0; j < 4; j++)
            dst[(size_t)(m0 + ty * 4 + i) * NB + n0 + tx * 4 + j] = acc[i][j];
}

// reduce partials [j][b] -> g_gbase [b][j], folding both biases
__global__ void gbase_reduce_kernel(const float* __restrict__ bih,
                                    const float* __restrict__ bhh) {
    int idx = blockIdx.x * blockDim.x + threadIdx.x;   // over NG*NB, [j][b]
    int j = idx >> 7;
    int b = idx & 127;
    float s = bih[j] + bhh[j];
    #pragma unroll
    for (int z = 0; z < 8; z++)
        s += g_bpart[(size_t)z * NG * NB + idx];
    g_gbase[(size_t)b * NG + j] = s;
}

// ---------------- LSTM elementwise cell -------------------------------------
__global__ void lstm_cell_kernel(int t) {
    int idx = blockIdx.x * blockDim.x + threadIdx.x;   // 128*256
    int b = idx >> 8;
    int h = idx & 255;
    const float* g = g_gates + b * NG;
    float xi = g[h];
    float xf = g[256 + h];
    float xg = g[512 + h];
    float xo = g[768 + h];
    float i_ = 1.f / (1.f + expf(-xi));
    float f_ = 1.f / (1.f + expf(-xf));
    float gg = tanhf(xg);
    float o_ = 1.f / (1.f + expf(-xo));
    float c = f_ * g_c[idx] + i_ * gg;
    float hn = o_ * tanhf(c);
    g_c[idx] = c;
    g_h[idx] = hn;
    g_Hall[t * NB * NH + idx] = hn;
}

// ---------------- fc: fp16 tensor-core GEMM (m16n8k16), fragment-major smem --
// out[(b*T+t)][v] = Hall[(t*B+b)][:] @ fc_W + fc_b
// M=4096, N=32000, K=256. BM=BN=128, BK=16, 8 warps (2x4), warp 64x32.
// Per k-iter: 1 k-step of m16n8k16 -> 16 MMA, 4 LDS.128 (A) + 4 LDS.64 (B).
// fp16 mantissa (11 bit) == tf32 mantissa; fp32 accumulate -> same accuracy class.
__global__ void __launch_bounds__(256) fc_f16_kernel(const float* __restrict__ A,
                                                     const float* __restrict__ Bw,
                                                     const float* __restrict__ bias,
                                                     float* __restrict__ out) {
    __shared__ __align__(16) uint32_t As[2][8 * 128];   // 8 M-chunks x (32 lanes x 4 regs)
    __shared__ __align__(16) __half  Bs[2][16 * 128];   // 16 N-chunks x (32 lanes x 4 halves)
    const int tid = threadIdx.x;
    const int m0 = blockIdx.y * 128, n0 = blockIdx.x * 128;
    const int lane = tid & 31, warp = tid >> 5;
    const int g = lane >> 2, tig = lane & 3;
    const int amb0 = (warp >> 2) * 4;
    const int bnb0 = (warp & 3) * 4;
    const int wm = (warp >> 2) * 64, wn = (warp & 3) * 32;

    // global load mapping
    const int a_row = tid >> 2;          // 0..63 (and +64)
    const int a_c = tid & 3;             // k quad: k = 4*a_c
    const int b_row = tid >> 5;          // k: 0..7 (and +8)
    const int b_col = (tid & 31) * 4;    // n quad
    const float* Ag = A + (size_t)(m0 + a_row) * NH + a_c * 4;
    const float* Bg = Bw + (size_t)b_row * NV + n0 + b_col;

    // A writer: (row rl, k=4c..4c+3) -> chunk a_mb, lane (rl&7)*4 + 2(c&1) [+1], reg (rl>>3)&1 + 2(c>>1)
    const int rl = a_row & 15;
    const int a_mb = a_row >> 4;         // 0..3 (+4 for row+64)
    const int a_tig = (a_c & 1) * 2;
    const int a_reg = ((rl >> 3) & 1) + 2 * (a_c >> 1);
    const int aw0 = a_mb * 128 + ((rl & 7) * 4 + a_tig) * 4 + a_reg;
    const int aw1 = (a_mb + 4) * 128 + ((rl & 7) * 4 + a_tig) * 4 + a_reg;
    // B writer (half granularity): (k, n) -> chunk n>>3, half idx ((n&7)*4 + (k&7)/2)*4 + (k>>3)*2 + (k&1)
    const int b_nb = b_col >> 3;
    const int b_nl = b_col & 7;          // 0 or 4
    const int bh0 = b_nb * 128 + b_nl * 16 + (b_row >> 1) * 4 + (b_row & 1);   // k = b_row
    const int bh1 = bh0 + 2;                                                   // k = b_row + 8

    float acc[4][4][4];
    #pragma unroll
    for (int i = 0; i < 4; i++)
        #pragma unroll
        for (int j = 0; j < 4; j++)
            #pragma unroll
            for (int r = 0; r < 4; r++) acc[i][j][r] = 0.f;

    float4 pa[2], pb[2];
    pa[0] = *(const float4*)(Ag);
    pa[1] = *(const float4*)(Ag + (size_t)64 * NH);
    pb[0] = *(const float4*)(Bg);
    pb[1] = *(const float4*)(Bg + (size_t)8 * NV);
    {
        As[0][aw0] = packh2(pa[0].x, pa[0].y);
        As[0][aw0 + 4] = packh2(pa[0].z, pa[0].w);
        As[0][aw1] = packh2(pa[1].x, pa[1].y);
        As[0][aw1 + 4] = packh2(pa[1].z, pa[1].w);
        Bs[0][bh0 +  0] = __float2half_rn(pb[0].x);
        Bs[0][bh0 + 16] = __float2half_rn(pb[0].y);
        Bs[0][bh0 + 32] = __float2half_rn(pb[0].z);
        Bs[0][bh0 + 48] = __float2half_rn(pb[0].w);
        Bs[0][bh1 +  0] = __float2half_rn(pb[1].x);
        Bs[0][bh1 + 16] = __float2half_rn(pb[1].y);
        Bs[0][bh1 + 32] = __float2half_rn(pb[1].z);
        Bs[0][bh1 + 48] = __float2half_rn(pb[1].w);
    }
    __syncthreads();

    #pragma unroll 1
    for (int it = 0; it < 16; it++) {
        const int cur = it & 1;
        if (it < 15) {
            const int k0 = (it + 1) * 16;
            pa[0] = *(const float4*)(Ag + k0);
            pa[1] = *(const float4*)(Ag + (size_t)64 * NH + k0);
            pb[0] = *(const float4*)(Bg + (size_t)k0 * NV);
            pb[1] = *(const float4*)(Bg + (size_t)(k0 + 8) * NV);
        }
        {
            uint4 af[4];
            uint2 bf[4];
            const uint32_t* Bu = (const uint32_t*)&Bs[cur][0];
            #pragma unroll
            for (int ti = 0; ti < 4; ti++)
                af[ti] = *(const uint4*)&As[cur][(amb0 + ti) * 128 + lane * 4];
            #pragma unroll
            for (int tj = 0; tj < 4; tj++)
                bf[tj] = *(const uint2*)&Bu[(bnb0 + tj) * 64 + lane * 2];
            #pragma unroll
            for (int ti = 0; ti < 4; ti++)
                #pragma unroll
                for (int tj = 0; tj < 4; tj++)
                    mma_f16(acc[ti][tj],
                            reinterpret_cast<const uint32_t*>(&af[ti]),
                            reinterpret_cast<const uint32_t*>(&bf[tj]));
        }
        if (it < 15) {
            const int nb = cur ^ 1;
            As[nb][aw0] = packh2(pa[0].x, pa[0].y);
            As[nb][aw0 + 4] = packh2(pa[0].z, pa[0].w);
            As[nb][aw1] = packh2(pa[1].x, pa[1].y);
            As[nb][aw1 + 4] = packh2(pa[1].z, pa[1].w);
            Bs[nb][bh0 +  0] = __float2half_rn(pb[0].x);
            Bs[nb][bh0 + 16] = __float2half_rn(pb[0].y);
            Bs[nb][bh0 + 32] = __float2half_rn(pb[0].z);
            Bs[nb][bh0 + 48] = __float2half_rn(pb[0].w);
            Bs[nb][bh1 +  0] = __float2half_rn(pb[1].x);
            Bs[nb][bh1 + 16] = __float2half_rn(pb[1].y);
            Bs[nb][bh1 + 32] = __float2half_rn(pb[1].z);
            Bs[nb][bh1 + 48] = __float2half_rn(pb[1].w);
        }
        __syncthreads();
    }

    // epilogue: row m = t*128 + b  ->  out row (b*NTT + t)
    #pragma unroll
    for (int ti = 0; ti < 4; ti++) {
        int mA = m0 + wm + ti * 16 + g;
        int mB = mA + 8;
        int tA = mA >> 7, bA = mA & 127;
        int tB = mB >> 7, bB = mB & 127;
        float* oA = out + (size_t)(bA * NTT + tA) * NV;
        float* oB = out + (size_t)(bB * NTT + tB) * NV;
        #pragma unroll
        for (int tj = 0; tj < 4; tj++) {
            int n = n0 + wn + tj * 8 + 2 * tig;
            float b0 = bias[n], b1 = bias[n + 1];
            float2 vA, vB;
            vA.x = acc[ti][tj][0] + b0; vA.y = acc[ti][tj][1] + b1;
            vB.x = acc[ti][tj][2] + b0; vB.y = acc[ti][tj][3] + b1;
            *(float2*)&oA[n] = vA;
            *(float2*)&oB[n] = vB;
        }
    }
}

// ---------------- launch ----------------------------------------------------
extern "C" void kernel_launch(void* const* d_in, const int* in_sizes, int n_in,
                              void* d_out, int out_size) {
    const float* features   = (const float*)d_in[0];
    const int*   captions   = (const int*)d_in[1];
    const float* embeddings = (const float*)d_in[2];
    const float* W_ih       = (const float*)d_in[3];
    const float* b_ih       = (const float*)d_in[4];
    const float* W_hh       = (const float*)d_in[5];
    const float* b_hh       = (const float*)d_in[6];
    const float* fc_W       = (const float*)d_in[7];
    const float* fc_b       = (const float*)d_in[8];
    // d_in[9..14] = attention weights: provably unused (softmax over length-1 axis == 1)
    const float* initH_W    = (const float*)d_in[15];
    const float* initH_b    = (const float*)d_in[16];
    const float* initC_W    = (const float*)d_in[17];
    const float* initC_b    = (const float*)d_in[18];
    float* out = (float*)d_out;

    void *p_embed_, *p_gemb_, *p_gbase_, *p_gates_, *p_h_, *p_Hall_;
    cudaGetSymbolAddress(&p_embed_, g_embed);
    cudaGetSymbolAddress(&p_gemb_,  g_gates_emb);
    cudaGetSymbolAddress(&p_gbase_, g_gbase);
    cudaGetSymbolAddress(&p_gates_, g_gates);
    cudaGetSymbolAddress(&p_h_,     g_h);
    cudaGetSymbolAddress(&p_Hall_,  g_Hall);
    float* p_embed = (float*)p_embed_;
    float* p_gemb  = (float*)p_gemb_;
    float* p_gbase = (float*)p_gbase_;
    float* p_gates = (float*)p_gates_;
    float* p_h     = (float*)p_h_;
    float* p_Hall  = (float*)p_Hall_;

    // 1) gather word embeddings
    gather_embed_kernel<<<(NTT * NB * NE + 255) / 256, 256>>>(captions, embeddings);

    // 2) gates_emb[t,b,:] = embed @ W_ih[:, :E]^T   (M=4096, N=1024, K=128)
    sgemm_nt64<<<dim3(NG / 64, (NTT * NB) / 64), 256>>>(
        p_embed, NE, W_ih, LDW, p_gemb, NG, NE, nullptr, nullptr);

    // 3) gates_base: K-split GEMM + deterministic transpose-reduce (+biases)
    gbase_part_kernel<<<dim3(NB / 64, NG / 64, 8), 256>>>(W_ih + NE, features);
    gbase_reduce_kernel<<<(NG * NB) / 256, 256>>>(b_ih, b_hh);

    // 4) h0, c0 via K-split GEMM + deterministic reduce
    init_part_kernel<<<dim3(NH / 64, NB / 64, 8), 256>>>(features, initH_W, 0);
    init_part_kernel<<<dim3(NH / 64, NB / 64, 8), 256>>>(features, initC_W, 1);
    init_reduce_kernel<<<NB, NH>>>(initH_b, initC_b);

    // 5) sequential LSTM steps (measured-best unfused loop)
    for (int t = 0; t < NTT; t++) {
        sgemm_nt64<<<dim3(NG / 64, NB / 64), 256>>>(
            p_h, NH, W_hh, NH, p_gates, NG, NH,
            p_gbase, p_gemb + (size_t)t * NB * NG);
        lstm_cell_kernel<<<NB, NH>>>(t);
    }

    // 6) fc projection: fp16 tensor-core GEMM (4096, 256) @ (256, 32000)
    fc_f16_kernel<<<dim3(NV / 128, (NTT * NB) / 128), 256>>>(p_Hall, fc_W, fc_b, out);
}